// round 10
// baseline (speedup 1.0000x reference)
#include <cuda_runtime.h>
#include <cstdint>

// ===========================================================================
// LoRALinear: out = x @ (W + A@B); bias tail written only if out_size has room.
//   x:[8192,4096] W:[4096,4096] bias:[4096] A:[4096,16] B:[16,4096], all f32
//
// R10: primary = packed fma.rn.f32x2 SIMT GEMM (exact fp32, ~4.3ms floor).
//      mma tf32 branch kept behind a 1-warp instruction PROBE:
//        probe ok  -> run R9 mma GEMM + raw-grounded check; f32x2 as repair
//        probe bad -> skip straight to f32x2
//      dur_us discriminates: ~5ms (mma instr broken) / ~9ms (pipeline bug) /
//      ~4ms (all good).
// ===========================================================================

#define SEQ  8192
#define DIN  4096
#define DOUT 4096
#define RANK 16

__device__ float g_WpT[(size_t)DOUT * DIN];   // 64 MB [n][k] (mma path, rna)
__device__ float g_Wp [(size_t)DIN * DOUT];   // 64 MB [k][n] (f32x2 path, exact)
__device__ float g_x32[(size_t)SEQ * DIN];    // 128 MB rna x (mma path)
__device__ int   g_flag;
__device__ int   g_ab_swap;
__device__ int   g_mma_ok;

// ---------------- helpers ---------------------------------------------------
__device__ __forceinline__ uint32_t smem_u32(const void* p) {
    uint32_t a;
    asm("{ .reg .u64 t; cvta.to.shared.u64 t, %1; cvt.u32.u64 %0, t; }" : "=r"(a) : "l"(p));
    return a;
}
__device__ __forceinline__ void cp16(uint32_t s, const void* g) {
    asm volatile("cp.async.cg.shared.global [%0], [%1], 16;" :: "r"(s), "l"(g) : "memory");
}
#define CP_COMMIT() asm volatile("cp.async.commit_group;" ::: "memory")
#define CP_WAIT(n)  asm volatile("cp.async.wait_group %0;" :: "n"(n) : "memory")

__device__ __forceinline__ float rna_tf32(float v) {
    uint32_t b;
    asm("cvt.rna.tf32.f32 %0, %1;" : "=r"(b) : "f"(v));
    return __uint_as_float(b);
}
__device__ __forceinline__ void mma_tf32(float* c, const uint32_t* a, const uint32_t* b) {
    asm volatile(
        "mma.sync.aligned.m16n8k8.row.col.f32.tf32.tf32.f32 "
        "{%0,%1,%2,%3}, {%4,%5,%6,%7}, {%8,%9}, {%0,%1,%2,%3};"
        : "+f"(c[0]), "+f"(c[1]), "+f"(c[2]), "+f"(c[3])
        : "r"(a[0]), "r"(a[1]), "r"(a[2]), "r"(a[3]), "r"(b[0]), "r"(b[1]));
}
// packed dual-fp32 FMA (sm_100+): d = a*b + d elementwise on {lo,hi}
__device__ __forceinline__ void fma2(unsigned long long& d,
                                     unsigned long long a, unsigned long long b) {
    asm("fma.rn.f32x2 %0, %1, %2, %0;" : "+l"(d) : "l"(a), "l"(b));
}
__device__ __forceinline__ unsigned long long dup2(float v) {
    unsigned long long r;
    uint32_t b = __float_as_uint(v);
    asm("mov.b64 %0, {%1, %1};" : "=l"(r) : "r"(b));
    return r;
}

// ---------------------------------------------------------------------------
// id: A vs B by mean-square (A scaled 1/sqrt(4096)); reset g_flag.
// ---------------------------------------------------------------------------
__global__ void id_kernel(const float* __restrict__ P0) {
    __shared__ float red[256];
    const int t = threadIdx.x;
    float s = 0.f;
    for (int i = t; i < 16384; i += 256) { float v = P0[i]; s += v * v; }
    red[t] = s;
    __syncthreads();
    for (int off = 128; off > 0; off >>= 1) {
        if (t < off) red[t] += red[t + off];
        __syncthreads();
    }
    if (t == 0) {
        g_ab_swap = (red[0] * (1.f / 16384.f) > 0.05f) ? 1 : 0;
        g_flag = 0;
    }
}

// ---------------------------------------------------------------------------
// probe: does mma.sync m16n8k8 tf32 actually compute? Exact small-int test.
// ---------------------------------------------------------------------------
__device__ __forceinline__ float pA(int m, int k) { return (float)((m * 3 + k * 5) % 7 - 3); }
__device__ __forceinline__ float pB(int k, int n) { return (float)((k * 2 + n * 3) % 5 - 2); }

__global__ void probe_kernel() {
    const int lane = threadIdx.x;
    const int g = lane >> 2, tq = lane & 3;
    uint32_t a[4], b[2];
    a[0] = __float_as_uint(pA(g, tq));
    a[1] = __float_as_uint(pA(g + 8, tq));
    a[2] = __float_as_uint(pA(g, tq + 4));
    a[3] = __float_as_uint(pA(g + 8, tq + 4));
    b[0] = __float_as_uint(pB(tq, g));
    b[1] = __float_as_uint(pB(tq + 4, g));
    float c[4] = {0.f, 0.f, 0.f, 0.f};
    mma_tf32(c, a, b);

    float ref[4] = {0.f, 0.f, 0.f, 0.f};
    for (int k = 0; k < 8; k++) {
        ref[0] += pA(g, k)     * pB(k, 2 * tq);
        ref[1] += pA(g, k)     * pB(k, 2 * tq + 1);
        ref[2] += pA(g + 8, k) * pB(k, 2 * tq);
        ref[3] += pA(g + 8, k) * pB(k, 2 * tq + 1);
    }
    bool ok = (c[0] == ref[0]) && (c[1] == ref[1]) && (c[2] == ref[2]) && (c[3] == ref[3]);
    ok = __all_sync(0xFFFFFFFFu, ok);
    if (lane == 0) g_mma_ok = ok ? 1 : 0;
}

// ---------------------------------------------------------------------------
// prep kernels
// ---------------------------------------------------------------------------
__global__ void round_x_kernel(const float4* __restrict__ x, float4* __restrict__ dst) {
    if (!g_mma_ok) return;
    size_t i = (size_t)blockIdx.x * blockDim.x + threadIdx.x;
    float4 v = x[i];
    v.x = rna_tf32(v.x); v.y = rna_tf32(v.y);
    v.z = rna_tf32(v.z); v.w = rna_tf32(v.w);
    dst[i] = v;
}

// WpT[n][k] = rna(W[k][n] + lora)   (mma path only)
__global__ void prep_T_kernel(const float* __restrict__ W,
                              const float* __restrict__ P0,
                              const float* __restrict__ P1) {
    if (!g_mma_ok) return;
    const float* A = g_ab_swap ? P1 : P0;
    const float* B = g_ab_swap ? P0 : P1;
    __shared__ float tW[32][33];
    __shared__ float tA[32][17];
    __shared__ float tB[16][33];
    const int n0 = blockIdx.x * 32;
    const int k0 = blockIdx.y * 32;
    const int tx = threadIdx.x, ty = threadIdx.y;
    const int t = ty * 32 + tx;
#pragma unroll
    for (int i = 0; i < 4; i++)
        tW[ty + 8 * i][tx] = W[(size_t)(k0 + ty + 8 * i) * DOUT + n0 + tx];
#pragma unroll
    for (int i = 0; i < 2; i++) {
        int e = t + 256 * i;
        tA[e / 16][e % 16] = A[(size_t)(k0 + e / 16) * RANK + (e % 16)];
        tB[e / 32][e % 32] = B[(size_t)(e / 32) * DOUT + n0 + (e % 32)];
    }
    __syncthreads();
#pragma unroll
    for (int i = 0; i < 4; i++) {
        int nn = ty + 8 * i;
        float acc = tW[tx][nn];
#pragma unroll
        for (int r = 0; r < RANK; r++) acc = fmaf(tA[tx][r], tB[r][nn], acc);
        g_WpT[(size_t)(n0 + nn) * DIN + k0 + tx] = rna_tf32(acc);
    }
}

// Wp[k][n] = W[k][n] + lora, EXACT fp32 (f32x2 path). Coalesced R/W.
__global__ void prep_kn_kernel(const float* __restrict__ W,
                               const float* __restrict__ P0,
                               const float* __restrict__ P1) {
    const float* A = g_ab_swap ? P1 : P0;
    const float* B = g_ab_swap ? P0 : P1;
    __shared__ float tA[32][17];
    __shared__ float tB[16][33];
    const int n0 = blockIdx.x * 32;
    const int k0 = blockIdx.y * 32;
    const int tx = threadIdx.x, ty = threadIdx.y;
    const int t = ty * 32 + tx;
#pragma unroll
    for (int i = 0; i < 2; i++) {
        int e = t + 256 * i;
        tA[e / 16][e % 16] = A[(size_t)(k0 + e / 16) * RANK + (e % 16)];
        tB[e / 32][e % 32] = B[(size_t)(e / 32) * DOUT + n0 + (e % 32)];
    }
    __syncthreads();
#pragma unroll
    for (int i = 0; i < 4; i++) {
        int kk = ty + 8 * i;
        float acc = W[(size_t)(k0 + kk) * DOUT + n0 + tx];
#pragma unroll
        for (int r = 0; r < RANK; r++) acc = fmaf(tA[kk][r], tB[r][tx], acc);
        g_Wp[(size_t)(k0 + kk) * DOUT + n0 + tx] = acc;
    }
}

__global__ void bias_copy_kernel(const float* __restrict__ b, float* __restrict__ dst) {
    int i = blockIdx.x * 256 + threadIdx.x;
    if (i < DOUT) dst[i] = b[i];
}

// ===========================================================================
// mma tf32 GEMM (R9 verbatim, gated on g_mma_ok).
// ===========================================================================
static constexpr int FBM = 128, FBN = 128, FBK = 16;
static constexpr int APAD = 20;
static constexpr int F_TILE_F = FBM * APAD;
static constexpr int F_STAGE_BYTES = 2 * F_TILE_F * 4;
static constexpr int FB_SMEM = 2 * F_STAGE_BYTES;       // 40960 < 48KB
static constexpr int F_NCHUNK = DIN / FBK;
static constexpr int FNT = DOUT / FBN;
static constexpr int FMT = SEQ / FBM;

__device__ __forceinline__ void fb_load_chunk(uint32_t su, int s, int m0, int n0,
                                              int kc, int tid) {
    uint32_t base = su + s * F_STAGE_BYTES;
    const float* ga = g_x32 + (size_t)m0 * DIN + kc;
#pragma unroll
    for (int j = 0; j < 2; j++) {
        int idx = j * 256 + tid;
        int row = idx >> 2, q = idx & 3;
        cp16(base + (row * APAD + q * 4) * 4, ga + (size_t)row * DIN + q * 4);
    }
    const float* gb = g_WpT + (size_t)n0 * DIN + kc;
    uint32_t baseB = base + F_TILE_F * 4;
#pragma unroll
    for (int j = 0; j < 2; j++) {
        int idx = j * 256 + tid;
        int row = idx >> 2, q = idx & 3;
        cp16(baseB + (row * APAD + q * 4) * 4, gb + (size_t)row * DIN + q * 4);
    }
}

__global__ __launch_bounds__(256)
void gemm_mma_kernel(float* __restrict__ out) {
    if (!g_mma_ok) return;
    extern __shared__ __align__(128) char smem[];
    const uint32_t su = smem_u32(smem);
    const int tid = threadIdx.x;
    const int wid = tid >> 5, lid = tid & 31;
    const int g = lid >> 2, tq = lid & 3;
    const int wm0 = (wid >> 2) * 64, wn0 = (wid & 3) * 32;

    const int bid   = blockIdx.x;
    const int group = bid / (8 * FNT);
    const int rem   = bid % (8 * FNT);
    const int m0 = (group * 8 + (rem % 8)) * FBM;
    const int n0 = (rem / 8) * FBN;

    float acc[4][4][4];
#pragma unroll
    for (int i = 0; i < 4; i++)
#pragma unroll
        for (int j = 0; j < 4; j++)
#pragma unroll
            for (int q = 0; q < 4; q++) acc[i][j][q] = 0.f;

    fb_load_chunk(su, 0, m0, n0, 0, tid);
    CP_COMMIT();

    for (int i = 0; i < F_NCHUNK; i++) {
        if (i + 1 < F_NCHUNK) {
            fb_load_chunk(su, (i + 1) & 1, m0, n0, (i + 1) * FBK, tid);
            CP_COMMIT();
            CP_WAIT(1);
        } else {
            CP_WAIT(0);
        }
        __syncthreads();

        const int s = i & 1;
        const uint32_t* As = reinterpret_cast<const uint32_t*>(smem + s * F_STAGE_BYTES);
        const uint32_t* Bs = As + F_TILE_F;
#pragma unroll
        for (int kb = 0; kb < 2; kb++) {
            uint32_t af[4][4], bf[4][2];
            const int kc = kb * 8 + tq;
#pragma unroll
            for (int mi = 0; mi < 4; mi++) {
                const uint32_t* p = As + (wm0 + mi * 16 + g) * APAD + kc;
                af[mi][0] = p[0];
                af[mi][1] = p[8 * APAD];
                af[mi][2] = p[4];
                af[mi][3] = p[8 * APAD + 4];
            }
#pragma unroll
            for (int ni = 0; ni < 4; ni++) {
                const uint32_t* p = Bs + (wn0 + ni * 8 + g) * APAD + kc;
                bf[ni][0] = p[0];
                bf[ni][1] = p[4];
            }
#pragma unroll
            for (int mi = 0; mi < 4; mi++)
#pragma unroll
                for (int ni = 0; ni < 4; ni++)
                    mma_tf32(acc[mi][ni], af[mi], bf[ni]);
        }
        __syncthreads();
    }

#pragma unroll
    for (int mi = 0; mi < 4; mi++) {
        const int row = m0 + wm0 + mi * 16 + g;
#pragma unroll
        for (int ni = 0; ni < 4; ni++) {
            const int col = n0 + wn0 + ni * 8 + tq * 2;
            *reinterpret_cast<float2*>(out + (size_t)row * DOUT + col) =
                make_float2(acc[mi][ni][0], acc[mi][ni][1]);
            *reinterpret_cast<float2*>(out + (size_t)(row + 8) * DOUT + col) =
                make_float2(acc[mi][ni][2], acc[mi][ni][3]);
        }
    }
}

// ===========================================================================
// Check (raw-input grounded; only meaningful after the mma path ran).
// ===========================================================================
__global__ void check_kernel(const float* __restrict__ out,
                             const float* __restrict__ x,
                             const float* __restrict__ W,
                             const float* __restrict__ P0,
                             const float* __restrict__ P1) {
    if (!g_mma_ok) return;
    const float* A = g_ab_swap ? P1 : P0;
    const float* B = g_ab_swap ? P0 : P1;
    const int s = blockIdx.x * 256 + threadIdx.x;
    const int m = (s >> 5) * 128 + ((s * 37) & 127);
    const int n = (s & 31) * 128 + ((s * 59) & 127);

    const float* xr = x + (size_t)m * DIN;
    float acc = 0.f;
    float la[RANK];
#pragma unroll
    for (int r = 0; r < RANK; r++) la[r] = 0.f;
    for (int k = 0; k < DIN; k++) {
        float xk = xr[k];
        acc = fmaf(xk, W[(size_t)k * DOUT + n], acc);
        const float* ar = A + (size_t)k * RANK;
#pragma unroll
        for (int r = 0; r < RANK; r++) la[r] = fmaf(xk, ar[r], la[r]);
    }
#pragma unroll
    for (int r = 0; r < RANK; r++) acc = fmaf(la[r], B[(size_t)r * DOUT + n], acc);

    float got = out[(size_t)m * DOUT + n];
    if (fabsf(got - acc) > 0.05f + 0.02f * fabsf(acc))
        atomicAdd(&g_flag, 1);
}

// ===========================================================================
// f32x2 SIMT GEMM: exact fp32 via packed fma.rn.f32x2 (2x fp32 pipe).
// CTA 128x128, BK=16, 256 threads (16x16), per-thread 8m x 8n (n paired).
// Register double-buffered plain loads; static smem 33.8 KB.
// Runs when mma is broken OR check flagged.
// ===========================================================================
static constexpr int P2 = 132;   // padded row floats (16B-multiple rows: 528B)

__global__ __launch_bounds__(256, 2)
void gemm_f32x2_kernel(const float* __restrict__ x, float* __restrict__ out) {
    if (g_mma_ok && g_flag == 0) return;
    __shared__ __align__(16) float Xs[2][16][P2];   // [k][m]
    __shared__ __align__(16) float Ws[2][16][P2];   // [k][n]
    const int t = threadIdx.x;
    const int tm2 = t >> 4, tn2 = t & 15;

    const int bid   = blockIdx.x;
    const int group = bid >> 8;           // /(8*32)
    const int rem   = bid & 255;
    const int m0 = (group * 8 + (rem & 7)) * 128;
    const int n0 = (rem >> 3) * 128;

    unsigned long long acc2[8][4];
#pragma unroll
    for (int i = 0; i < 8; i++)
#pragma unroll
        for (int j = 0; j < 4; j++) acc2[i][j] = 0ULL;

    float4 rx[2], rw[2];
    // --- load chunk kc into registers ---
    auto LOADG = [&](int kc) {
#pragma unroll
        for (int j = 0; j < 2; j++) {
            int idx = j * 256 + t;
            int m = idx >> 2, q = idx & 3;
            rx[j] = *reinterpret_cast<const float4*>(
                x + (size_t)(m0 + m) * DIN + kc + q * 4);
            int kk = idx >> 5, qn = idx & 31;
            rw[j] = *reinterpret_cast<const float4*>(
                g_Wp + (size_t)(kc + kk) * DOUT + n0 + qn * 4);
        }
    };
    // --- store registers into smem buffer (x transposed to [k][m]) ---
    auto STORES = [&](int buf) {
#pragma unroll
        for (int j = 0; j < 2; j++) {
            int idx = j * 256 + t;
            int m = idx >> 2, q = idx & 3;
            Xs[buf][q * 4 + 0][m] = rx[j].x;
            Xs[buf][q * 4 + 1][m] = rx[j].y;
            Xs[buf][q * 4 + 2][m] = rx[j].z;
            Xs[buf][q * 4 + 3][m] = rx[j].w;
            int kk = idx >> 5, qn = idx & 31;
            *reinterpret_cast<float4*>(&Ws[buf][kk][qn * 4]) = rw[j];
        }
    };

    LOADG(0);
    STORES(0);
    __syncthreads();

    for (int i = 0; i < DIN / 16; i++) {
        if (i + 1 < DIN / 16) LOADG((i + 1) * 16);
        const int buf = i & 1;
#pragma unroll
        for (int kk = 0; kk < 16; kk++) {
            unsigned long long b2[4];
#pragma unroll
            for (int jj = 0; jj < 4; jj++)
                b2[jj] = *reinterpret_cast<const unsigned long long*>(
                    &Ws[buf][kk][tn2 * 2 + 32 * jj]);
#pragma unroll
            for (int ii = 0; ii < 8; ii++) {
                unsigned long long a2 = dup2(Xs[buf][kk][tm2 + 16 * ii]);
#pragma unroll
                for (int jj = 0; jj < 4; jj++)
                    fma2(acc2[ii][jj], a2, b2[jj]);
            }
        }
        if (i + 1 < DIN / 16) STORES(buf ^ 1);
        __syncthreads();
    }

#pragma unroll
    for (int ii = 0; ii < 8; ii++) {
        const int row = m0 + tm2 + 16 * ii;
#pragma unroll
        for (int jj = 0; jj < 4; jj++) {
            uint32_t lo, hi;
            asm("mov.b64 {%0, %1}, %2;" : "=r"(lo), "=r"(hi) : "l"(acc2[ii][jj]));
            *reinterpret_cast<float2*>(out + (size_t)row * DOUT + n0 + tn2 * 2 + 32 * jj) =
                make_float2(__uint_as_float(lo), __uint_as_float(hi));
        }
    }
}

// ---------------------------------------------------------------------------
extern "C" void kernel_launch(void* const* d_in, const int* in_sizes, int n_in,
                              void* d_out, int out_size) {
    const float *x = nullptr, *W = nullptr, *bias = nullptr;
    const float *P0 = nullptr, *P1 = nullptr;
    for (int i = 0; i < n_in; i++) {
        const float* p = (const float*)d_in[i];
        int sz = in_sizes[i];
        if      (sz == SEQ * DIN)   x = p;
        else if (sz == DIN * DOUT)  W = p;
        else if (sz == DOUT)        bias = p;
        else if (sz == DIN * RANK) { if (!P0) P0 = p; else P1 = p; }
    }
    if (!x || !W || !bias || !P0 || !P1) {
        x = (const float*)d_in[0]; W = (const float*)d_in[1];
        bias = (const float*)d_in[2];
        P0 = (const float*)d_in[3]; P1 = (const float*)d_in[4];
    }
    float* out = (float*)d_out;

    id_kernel<<<1, 256>>>(P0);
    probe_kernel<<<1, 32>>>();
    round_x_kernel<<<(SEQ * DIN / 4) / 256, 256>>>((const float4*)x, (float4*)g_x32);
    prep_T_kernel<<<dim3(DOUT / 32, DIN / 32), dim3(32, 8)>>>(W, P0, P1);
    prep_kn_kernel<<<dim3(DOUT / 32, DIN / 32), dim3(32, 8)>>>(W, P0, P1);

    if (out_size >= SEQ * DOUT + DOUT)
        bias_copy_kernel<<<(DOUT + 255) / 256, 256>>>(bias, out + (size_t)SEQ * DOUT);

    gemm_mma_kernel<<<FMT * FNT, 256, FB_SMEM>>>(out);
    check_kernel<<<8, 256>>>(out, x, W, P0, P1);
    gemm_f32x2_kernel<<<(SEQ / 128) * (DOUT / 128), 256>>>(x, out);
}

// round 11
// speedup vs baseline: 6.6537x; 6.6537x over previous
#include <cuda_runtime.h>
#include <cstdint>

// ===========================================================================
// LoRALinear: out = x @ (W + A@B); bias tail written only if out_size has room.
//   x:[8192,4096] W:[4096,4096] bias:[4096] A:[4096,16] B:[16,4096], all f32
//
// R11: R10 evidence: mma.sync INSTRUCTION works (probe passed), prep_kn/g_Wp
//      validated, but the cp.async-pipelined mma GEMM output was flagged.
//      -> primary GEMM = SIMPLE SYNCHRONOUS mma tf32 (no cp.async, static
//         smem, syncthreads-fenced, probe-verified fragment mapping verbatim).
//      -> check vs validated g_Wp, parallelized (3.8ms -> ~40us).
//      -> f32x2 exact-fp32 fallback gated on the check flag.
//      rel_err discriminates the writer: ~3e-4 = mma path, ~1.2e-6 = fallback.
// ===========================================================================

#define SEQ  8192
#define DIN  4096
#define DOUT 4096
#define RANK 16

__device__ float g_Wp [(size_t)DIN * DOUT];   // 64 MB [k][n] exact W+lora (VALIDATED)
__device__ float g_WpT[(size_t)DOUT * DIN];   // 64 MB [n][k] rna(tf32) of g_Wp
__device__ int   g_flag;
__device__ int   g_ab_swap;

// ---------------- helpers ---------------------------------------------------
__device__ __forceinline__ float rna_tf32(float v) {
    uint32_t b;
    asm("cvt.rna.tf32.f32 %0, %1;" : "=r"(b) : "f"(v));
    return __uint_as_float(b);
}
__device__ __forceinline__ void mma_tf32(float* c, const uint32_t* a, const uint32_t* b) {
    asm volatile(
        "mma.sync.aligned.m16n8k8.row.col.f32.tf32.tf32.f32 "
        "{%0,%1,%2,%3}, {%4,%5,%6,%7}, {%8,%9}, {%0,%1,%2,%3};"
        : "+f"(c[0]), "+f"(c[1]), "+f"(c[2]), "+f"(c[3])
        : "r"(a[0]), "r"(a[1]), "r"(a[2]), "r"(a[3]), "r"(b[0]), "r"(b[1]));
}
__device__ __forceinline__ void fma2(unsigned long long& d,
                                     unsigned long long a, unsigned long long b) {
    asm("fma.rn.f32x2 %0, %1, %2, %0;" : "+l"(d) : "l"(a), "l"(b));
}
__device__ __forceinline__ unsigned long long dup2(float v) {
    unsigned long long r;
    uint32_t b = __float_as_uint(v);
    asm("mov.b64 %0, {%1, %1};" : "=l"(r) : "r"(b));
    return r;
}

// ---------------------------------------------------------------------------
// id: A vs B by mean-square (A scaled 1/sqrt(4096)); reset g_flag.
// ---------------------------------------------------------------------------
__global__ void id_kernel(const float* __restrict__ P0) {
    __shared__ float red[256];
    const int t = threadIdx.x;
    float s = 0.f;
    for (int i = t; i < 16384; i += 256) { float v = P0[i]; s += v * v; }
    red[t] = s;
    __syncthreads();
    for (int off = 128; off > 0; off >>= 1) {
        if (t < off) red[t] += red[t + off];
        __syncthreads();
    }
    if (t == 0) {
        g_ab_swap = (red[0] * (1.f / 16384.f) > 0.05f) ? 1 : 0;
        g_flag = 0;
    }
}

// ---------------------------------------------------------------------------
// prep_kn: g_Wp[k][n] = W[k][n] + (A@B)[k][n]  EXACT fp32  (validated in R10)
// ---------------------------------------------------------------------------
__global__ void prep_kn_kernel(const float* __restrict__ W,
                               const float* __restrict__ P0,
                               const float* __restrict__ P1) {
    const float* A = g_ab_swap ? P1 : P0;
    const float* B = g_ab_swap ? P0 : P1;
    __shared__ float tA[32][17];
    __shared__ float tB[16][33];
    const int n0 = blockIdx.x * 32;
    const int k0 = blockIdx.y * 32;
    const int tx = threadIdx.x, ty = threadIdx.y;
    const int t = ty * 32 + tx;
#pragma unroll
    for (int i = 0; i < 2; i++) {
        int e = t + 256 * i;
        tA[e / 16][e % 16] = A[(size_t)(k0 + e / 16) * RANK + (e % 16)];
        tB[e / 32][e % 32] = B[(size_t)(e / 32) * DOUT + n0 + (e % 32)];
    }
    __syncthreads();
#pragma unroll
    for (int i = 0; i < 4; i++) {
        int kk = ty + 8 * i;
        float acc = W[(size_t)(k0 + kk) * DOUT + n0 + tx];
#pragma unroll
        for (int r = 0; r < RANK; r++) acc = fmaf(tA[kk][r], tB[r][tx], acc);
        g_Wp[(size_t)(k0 + kk) * DOUT + n0 + tx] = acc;
    }
}

// ---------------------------------------------------------------------------
// transpose + rna: g_WpT[n][k] = rna_tf32(g_Wp[k][n])
// ---------------------------------------------------------------------------
__global__ void transpose_rna_kernel() {
    __shared__ float t[32][33];
    const int k0 = blockIdx.x * 32;
    const int n0 = blockIdx.y * 32;
    const int tx = threadIdx.x, ty = threadIdx.y;   // 32 x 8
#pragma unroll
    for (int i = 0; i < 4; i++)
        t[ty + 8 * i][tx] = g_Wp[(size_t)(k0 + ty + 8 * i) * DOUT + n0 + tx];
    __syncthreads();
#pragma unroll
    for (int i = 0; i < 4; i++)
        g_WpT[(size_t)(n0 + ty + 8 * i) * DIN + k0 + tx] = rna_tf32(t[tx][ty + 8 * i]);
}

__global__ void bias_copy_kernel(const float* __restrict__ b, float* __restrict__ dst) {
    int i = blockIdx.x * 256 + threadIdx.x;
    if (i < DOUT) dst[i] = b[i];
}

// ===========================================================================
// PRIMARY: simple synchronous mma tf32 GEMM. CTA 128x128, BK=16, 256 threads
// (8 warps 2x4, warp tile 64x32). Static smem, single buffer, no cp.async.
// Fragment mapping identical to the probe that PASSED on hardware.
// ===========================================================================
static constexpr int APAD = 20;            // (20g+tq) mod 32 hits all 32 banks
static constexpr int FNT = DOUT / 128;     // 32
static constexpr int FMT = SEQ / 128;      // 64

__global__ __launch_bounds__(256, 2)
void gemm_mma_kernel(const float* __restrict__ x, float* __restrict__ out) {
    __shared__ __align__(16) float sA[128 * APAD];
    __shared__ __align__(16) float sB[128 * APAD];
    const int tid = threadIdx.x;
    const int wid = tid >> 5, lid = tid & 31;
    const int g = lid >> 2, tq = lid & 3;
    const int wm0 = (wid >> 2) * 64, wn0 = (wid & 3) * 32;

    // supertile swizzle: groups of 8 m-tiles sweep all n-tiles (L2 reuse)
    const int bid = blockIdx.x;
    const int m0 = ((bid >> 8) * 8 + (bid & 7)) * 128;
    const int n0 = ((bid & 255) >> 3) * 128;

    float acc[4][4][4];
#pragma unroll
    for (int i = 0; i < 4; i++)
#pragma unroll
        for (int j = 0; j < 4; j++)
#pragma unroll
            for (int q = 0; q < 4; q++) acc[i][j][q] = 0.f;

    for (int i = 0; i < DIN / 16; i++) {
        __syncthreads();                      // prev-iter reads done
#pragma unroll
        for (int j = 0; j < 2; j++) {         // 512 float4 loads per operand
            int idx = j * 256 + tid;
            int row = idx >> 2, q = idx & 3;
            float4 va = *reinterpret_cast<const float4*>(
                x + (size_t)(m0 + row) * DIN + i * 16 + q * 4);
            va.x = rna_tf32(va.x); va.y = rna_tf32(va.y);
            va.z = rna_tf32(va.z); va.w = rna_tf32(va.w);
            *reinterpret_cast<float4*>(sA + row * APAD + q * 4) = va;
            float4 vb = *reinterpret_cast<const float4*>(
                g_WpT + (size_t)(n0 + row) * DIN + i * 16 + q * 4);
            *reinterpret_cast<float4*>(sB + row * APAD + q * 4) = vb;
        }
        __syncthreads();                      // tile ready

        const uint32_t* As = reinterpret_cast<const uint32_t*>(sA);
        const uint32_t* Bs = reinterpret_cast<const uint32_t*>(sB);
#pragma unroll
        for (int kb = 0; kb < 2; kb++) {
            uint32_t af[4][4], bf[4][2];
            const int kc = kb * 8 + tq;
#pragma unroll
            for (int mi = 0; mi < 4; mi++) {
                const uint32_t* p = As + (wm0 + mi * 16 + g) * APAD + kc;
                af[mi][0] = p[0];
                af[mi][1] = p[8 * APAD];
                af[mi][2] = p[4];
                af[mi][3] = p[8 * APAD + 4];
            }
#pragma unroll
            for (int ni = 0; ni < 4; ni++) {
                const uint32_t* p = Bs + (wn0 + ni * 8 + g) * APAD + kc;
                bf[ni][0] = p[0];
                bf[ni][1] = p[4];
            }
#pragma unroll
            for (int mi = 0; mi < 4; mi++)
#pragma unroll
                for (int ni = 0; ni < 4; ni++)
                    mma_tf32(acc[mi][ni], af[mi], bf[ni]);
        }
    }

#pragma unroll
    for (int mi = 0; mi < 4; mi++) {
        const int row = m0 + wm0 + mi * 16 + g;
#pragma unroll
        for (int ni = 0; ni < 4; ni++) {
            const int col = n0 + wn0 + ni * 8 + tq * 2;
            *reinterpret_cast<float2*>(out + (size_t)row * DOUT + col) =
                make_float2(acc[mi][ni][0], acc[mi][ni][1]);
            *reinterpret_cast<float2*>(out + (size_t)(row + 8) * DOUT + col) =
                make_float2(acc[mi][ni][2], acc[mi][ni][3]);
        }
    }
}

// ===========================================================================
// Fast check: one sample per 128x128 tile vs validated g_Wp. 2048 blocks.
// ===========================================================================
__global__ void check_kernel(const float* __restrict__ out,
                             const float* __restrict__ x) {
    const int b = blockIdx.x;                       // 0..2047
    const int m = (b >> 5) * 128 + ((b * 37) & 127);
    const int n = (b & 31) * 128 + ((b * 59) & 127);
    const int t = threadIdx.x;                      // 128
    float s = 0.f;
    for (int k = t; k < DIN; k += 128)
        s = fmaf(x[(size_t)m * DIN + k], g_Wp[(size_t)k * DOUT + n], s);
    __shared__ float red[128];
    red[t] = s;
    __syncthreads();
    for (int o = 64; o > 0; o >>= 1) {
        if (t < o) red[t] += red[t + o];
        __syncthreads();
    }
    if (t == 0) {
        float acc = red[0];
        float got = out[(size_t)m * DOUT + n];
        if (fabsf(got - acc) > 0.05f + 0.02f * fabsf(acc))
            atomicAdd(&g_flag, 1);
    }
}

// ===========================================================================
// Fallback: exact fp32 via packed fma.rn.f32x2 (validated in R10).
// Runs only if the check flagged the mma output.
// ===========================================================================
static constexpr int P2 = 132;

__global__ __launch_bounds__(256, 2)
void gemm_f32x2_kernel(const float* __restrict__ x, float* __restrict__ out) {
    if (g_flag == 0) return;
    __shared__ __align__(16) float Xs[2][16][P2];
    __shared__ __align__(16) float Ws[2][16][P2];
    const int t = threadIdx.x;
    const int tm2 = t >> 4, tn2 = t & 15;

    const int bid = blockIdx.x;
    const int m0 = ((bid >> 8) * 8 + (bid & 7)) * 128;
    const int n0 = ((bid & 255) >> 3) * 128;

    unsigned long long acc2[8][4];
#pragma unroll
    for (int i = 0; i < 8; i++)
#pragma unroll
        for (int j = 0; j < 4; j++) acc2[i][j] = 0ULL;

    float4 rx[2], rw[2];
    auto LOADG = [&](int kc) {
#pragma unroll
        for (int j = 0; j < 2; j++) {
            int idx = j * 256 + t;
            int m = idx >> 2, q = idx & 3;
            rx[j] = *reinterpret_cast<const float4*>(
                x + (size_t)(m0 + m) * DIN + kc + q * 4);
            int kk = idx >> 5, qn = idx & 31;
            rw[j] = *reinterpret_cast<const float4*>(
                g_Wp + (size_t)(kc + kk) * DOUT + n0 + qn * 4);
        }
    };
    auto STORES = [&](int buf) {
#pragma unroll
        for (int j = 0; j < 2; j++) {
            int idx = j * 256 + t;
            int m = idx >> 2, q = idx & 3;
            Xs[buf][q * 4 + 0][m] = rx[j].x;
            Xs[buf][q * 4 + 1][m] = rx[j].y;
            Xs[buf][q * 4 + 2][m] = rx[j].z;
            Xs[buf][q * 4 + 3][m] = rx[j].w;
            int kk = idx >> 5, qn = idx & 31;
            *reinterpret_cast<float4*>(&Ws[buf][kk][qn * 4]) = rw[j];
        }
    };

    LOADG(0);
    STORES(0);
    __syncthreads();

    for (int i = 0; i < DIN / 16; i++) {
        if (i + 1 < DIN / 16) LOADG((i + 1) * 16);
        const int buf = i & 1;
#pragma unroll
        for (int kk = 0; kk < 16; kk++) {
            unsigned long long b2[4];
#pragma unroll
            for (int jj = 0; jj < 4; jj++)
                b2[jj] = *reinterpret_cast<const unsigned long long*>(
                    &Ws[buf][kk][tn2 * 2 + 32 * jj]);
#pragma unroll
            for (int ii = 0; ii < 8; ii++) {
                unsigned long long a2 = dup2(Xs[buf][kk][tm2 + 16 * ii]);
#pragma unroll
                for (int jj = 0; jj < 4; jj++)
                    fma2(acc2[ii][jj], a2, b2[jj]);
            }
        }
        if (i + 1 < DIN / 16) STORES(buf ^ 1);
        __syncthreads();
    }

#pragma unroll
    for (int ii = 0; ii < 8; ii++) {
        const int row = m0 + tm2 + 16 * ii;
#pragma unroll
        for (int jj = 0; jj < 4; jj++) {
            uint32_t lo, hi;
            asm("mov.b64 {%0, %1}, %2;" : "=r"(lo), "=r"(hi) : "l"(acc2[ii][jj]));
            *reinterpret_cast<float2*>(out + (size_t)row * DOUT + n0 + tn2 * 2 + 32 * jj) =
                make_float2(__uint_as_float(lo), __uint_as_float(hi));
        }
    }
}

// ---------------------------------------------------------------------------
extern "C" void kernel_launch(void* const* d_in, const int* in_sizes, int n_in,
                              void* d_out, int out_size) {
    const float *x = nullptr, *W = nullptr, *bias = nullptr;
    const float *P0 = nullptr, *P1 = nullptr;
    for (int i = 0; i < n_in; i++) {
        const float* p = (const float*)d_in[i];
        int sz = in_sizes[i];
        if      (sz == SEQ * DIN)   x = p;
        else if (sz == DIN * DOUT)  W = p;
        else if (sz == DOUT)        bias = p;
        else if (sz == DIN * RANK) { if (!P0) P0 = p; else P1 = p; }
    }
    if (!x || !W || !bias || !P0 || !P1) {
        x = (const float*)d_in[0]; W = (const float*)d_in[1];
        bias = (const float*)d_in[2];
        P0 = (const float*)d_in[3]; P1 = (const float*)d_in[4];
    }
    float* out = (float*)d_out;

    id_kernel<<<1, 256>>>(P0);
    prep_kn_kernel<<<dim3(DOUT / 32, DIN / 32), dim3(32, 8)>>>(W, P0, P1);
    transpose_rna_kernel<<<dim3(DIN / 32, DOUT / 32), dim3(32, 8)>>>();

    if (out_size >= SEQ * DOUT + DOUT)
        bias_copy_kernel<<<(DOUT + 255) / 256, 256>>>(bias, out + (size_t)SEQ * DOUT);

    gemm_mma_kernel<<<FMT * FNT, 256>>>(x, out);
    check_kernel<<<2048, 128>>>(out, x);
    gemm_f32x2_kernel<<<FMT * FNT, 256>>>(x, out);
}

// round 13
// speedup vs baseline: 7.0070x; 1.0531x over previous
#include <cuda_runtime.h>
#include <cstdint>

// ===========================================================================
// LoRALinear: out = x @ (W + A@B); bias tail written only if out_size has room.
//   x:[8192,4096] W:[4096,4096] bias:[4096] A:[4096,16] B:[16,4096], all f32
//
// R13 = R12 resubmitted verbatim (R12 was a container/infra failure; no data).
// From R11 WIN @2307us (tf32 mma path confirmed working):
//   - GEMM: register-double-buffered smem pipeline (plain LDG, NO cp.async --
//     that was the R9/R10 corruption source). Fragment code byte-identical to
//     the probe-verified mapping.
//   - prep: single pass emits g_Wp[k][n] (exact) AND g_WpT[n][k] (rna tf32);
//     separate transpose kernel deleted.
//   - safety net: grounded sampled check + gated exact-fp32 f32x2 fallback.
// ===========================================================================

#define SEQ  8192
#define DIN  4096
#define DOUT 4096
#define RANK 16

__device__ float g_Wp [(size_t)DIN * DOUT];   // 64 MB [k][n] exact W+lora
__device__ float g_WpT[(size_t)DOUT * DIN];   // 64 MB [n][k] rna(tf32)
__device__ int   g_flag;
__device__ int   g_ab_swap;

// ---------------- helpers ---------------------------------------------------
__device__ __forceinline__ float rna_tf32(float v) {
    uint32_t b;
    asm("cvt.rna.tf32.f32 %0, %1;" : "=r"(b) : "f"(v));
    return __uint_as_float(b);
}
__device__ __forceinline__ void mma_tf32(float* c, const uint32_t* a, const uint32_t* b) {
    asm volatile(
        "mma.sync.aligned.m16n8k8.row.col.f32.tf32.tf32.f32 "
        "{%0,%1,%2,%3}, {%4,%5,%6,%7}, {%8,%9}, {%0,%1,%2,%3};"
        : "+f"(c[0]), "+f"(c[1]), "+f"(c[2]), "+f"(c[3])
        : "r"(a[0]), "r"(a[1]), "r"(a[2]), "r"(a[3]), "r"(b[0]), "r"(b[1]));
}
__device__ __forceinline__ void fma2(unsigned long long& d,
                                     unsigned long long a, unsigned long long b) {
    asm("fma.rn.f32x2 %0, %1, %2, %0;" : "+l"(d) : "l"(a), "l"(b));
}
__device__ __forceinline__ unsigned long long dup2(float v) {
    unsigned long long r;
    uint32_t b = __float_as_uint(v);
    asm("mov.b64 %0, {%1, %1};" : "=l"(r) : "r"(b));
    return r;
}

// ---------------------------------------------------------------------------
// id: A vs B by mean-square (A scaled 1/sqrt(4096)); reset g_flag.
// ---------------------------------------------------------------------------
__global__ void id_kernel(const float* __restrict__ P0) {
    __shared__ float red[256];
    const int t = threadIdx.x;
    float s = 0.f;
    for (int i = t; i < 16384; i += 256) { float v = P0[i]; s += v * v; }
    red[t] = s;
    __syncthreads();
    for (int off = 128; off > 0; off >>= 1) {
        if (t < off) red[t] += red[t + off];
        __syncthreads();
    }
    if (t == 0) {
        g_ab_swap = (red[0] * (1.f / 16384.f) > 0.05f) ? 1 : 0;
        g_flag = 0;
    }
}

// ---------------------------------------------------------------------------
// prep: g_Wp[k][n] = W + lora (exact)  AND  g_WpT[n][k] = rna(g_Wp) fused.
// ---------------------------------------------------------------------------
__global__ void prep_kn_kernel(const float* __restrict__ W,
                               const float* __restrict__ P0,
                               const float* __restrict__ P1) {
    const float* A = g_ab_swap ? P1 : P0;
    const float* B = g_ab_swap ? P0 : P1;
    __shared__ float tA[32][17];
    __shared__ float tB[16][33];
    __shared__ float tO[32][33];
    const int n0 = blockIdx.x * 32;
    const int k0 = blockIdx.y * 32;
    const int tx = threadIdx.x, ty = threadIdx.y;   // 32 x 8
    const int t = ty * 32 + tx;
#pragma unroll
    for (int i = 0; i < 2; i++) {
        int e = t + 256 * i;
        tA[e / 16][e % 16] = A[(size_t)(k0 + e / 16) * RANK + (e % 16)];
        tB[e / 32][e % 32] = B[(size_t)(e / 32) * DOUT + n0 + (e % 32)];
    }
    __syncthreads();
#pragma unroll
    for (int i = 0; i < 4; i++) {
        int kk = ty + 8 * i;
        float acc = W[(size_t)(k0 + kk) * DOUT + n0 + tx];
#pragma unroll
        for (int r = 0; r < RANK; r++) acc = fmaf(tA[kk][r], tB[r][tx], acc);
        g_Wp[(size_t)(k0 + kk) * DOUT + n0 + tx] = acc;
        tO[kk][tx] = acc;
    }
    __syncthreads();
#pragma unroll
    for (int i = 0; i < 4; i++) {
        int nn = ty + 8 * i;
        g_WpT[(size_t)(n0 + nn) * DIN + k0 + tx] = rna_tf32(tO[tx][nn]);
    }
}

__global__ void bias_copy_kernel(const float* __restrict__ b, float* __restrict__ dst) {
    int i = blockIdx.x * 256 + threadIdx.x;
    if (i < DOUT) dst[i] = b[i];
}

// ===========================================================================
// PRIMARY: mma tf32 GEMM, register-double-buffered smem pipeline (plain LDG).
// CTA 128x128, BK=16, 256 threads (8 warps 2x4, warp tile 64x32).
// Static smem 2 x 2 x 128 x 20 x 4 = 40960 B.
// ===========================================================================
static constexpr int APAD = 20;            // (20g+tq) mod 32 hits all 32 banks
static constexpr int FNT = DOUT / 128;     // 32
static constexpr int FMT = SEQ / 128;      // 64

__global__ __launch_bounds__(256, 2)
void gemm_mma_kernel(const float* __restrict__ x, float* __restrict__ out) {
    __shared__ __align__(16) float sA[2][128 * APAD];
    __shared__ __align__(16) float sB[2][128 * APAD];
    const int tid = threadIdx.x;
    const int wid = tid >> 5, lid = tid & 31;
    const int g = lid >> 2, tq = lid & 3;
    const int wm0 = (wid >> 2) * 64, wn0 = (wid & 3) * 32;

    // supertile swizzle: groups of 8 m-tiles sweep all n-tiles (L2 reuse)
    const int bid = blockIdx.x;
    const int m0 = ((bid >> 8) * 8 + (bid & 7)) * 128;
    const int n0 = ((bid & 255) >> 3) * 128;

    const int ldrow = tid >> 2, ldq = tid & 3;            // my LDG/STS slots
    const float* gx = x     + (size_t)(m0 + ldrow) * DIN + ldq * 4;
    const float* gw = g_WpT + (size_t)(n0 + ldrow) * DIN + ldq * 4;
    const float* gx2 = gx + (size_t)64 * DIN;             // rows 64..127
    const float* gw2 = gw + (size_t)64 * DIN;

    float acc[4][4][4];
#pragma unroll
    for (int i = 0; i < 4; i++)
#pragma unroll
        for (int j = 0; j < 4; j++)
#pragma unroll
            for (int q = 0; q < 4; q++) acc[i][j][q] = 0.f;

    float4 ra0, ra1, rb0, rb1;
    auto LOADG = [&](int kc) {
        ra0 = *reinterpret_cast<const float4*>(gx  + kc);
        ra1 = *reinterpret_cast<const float4*>(gx2 + kc);
        rb0 = *reinterpret_cast<const float4*>(gw  + kc);
        rb1 = *reinterpret_cast<const float4*>(gw2 + kc);
    };
    auto STORES = [&](int buf) {
        float4 va = ra0;
        va.x = rna_tf32(va.x); va.y = rna_tf32(va.y);
        va.z = rna_tf32(va.z); va.w = rna_tf32(va.w);
        *reinterpret_cast<float4*>(&sA[buf][ldrow * APAD + ldq * 4]) = va;
        va = ra1;
        va.x = rna_tf32(va.x); va.y = rna_tf32(va.y);
        va.z = rna_tf32(va.z); va.w = rna_tf32(va.w);
        *reinterpret_cast<float4*>(&sA[buf][(ldrow + 64) * APAD + ldq * 4]) = va;
        *reinterpret_cast<float4*>(&sB[buf][ldrow * APAD + ldq * 4]) = rb0;
        *reinterpret_cast<float4*>(&sB[buf][(ldrow + 64) * APAD + ldq * 4]) = rb1;
    };

    LOADG(0);
    STORES(0);
    __syncthreads();

    for (int i = 0; i < DIN / 16; i++) {
        if (i + 1 < DIN / 16) LOADG((i + 1) * 16);

        const int buf = i & 1;
        const uint32_t* As = reinterpret_cast<const uint32_t*>(sA[buf]);
        const uint32_t* Bs = reinterpret_cast<const uint32_t*>(sB[buf]);
#pragma unroll
        for (int kb = 0; kb < 2; kb++) {
            uint32_t af[4][4], bf[4][2];
            const int kc = kb * 8 + tq;
#pragma unroll
            for (int mi = 0; mi < 4; mi++) {
                const uint32_t* p = As + (wm0 + mi * 16 + g) * APAD + kc;
                af[mi][0] = p[0];
                af[mi][1] = p[8 * APAD];
                af[mi][2] = p[4];
                af[mi][3] = p[8 * APAD + 4];
            }
#pragma unroll
            for (int ni = 0; ni < 4; ni++) {
                const uint32_t* p = Bs + (wn0 + ni * 8 + g) * APAD + kc;
                bf[ni][0] = p[0];
                bf[ni][1] = p[4];
            }
#pragma unroll
            for (int mi = 0; mi < 4; mi++)
#pragma unroll
                for (int ni = 0; ni < 4; ni++)
                    mma_tf32(acc[mi][ni], af[mi], bf[ni]);
        }

        if (i + 1 < DIN / 16) STORES(buf ^ 1);   // buf^1 reads finished at i-1
        __syncthreads();
    }

#pragma unroll
    for (int mi = 0; mi < 4; mi++) {
        const int row = m0 + wm0 + mi * 16 + g;
#pragma unroll
        for (int ni = 0; ni < 4; ni++) {
            const int col = n0 + wn0 + ni * 8 + tq * 2;
            *reinterpret_cast<float2*>(out + (size_t)row * DOUT + col) =
                make_float2(acc[mi][ni][0], acc[mi][ni][1]);
            *reinterpret_cast<float2*>(out + (size_t)(row + 8) * DOUT + col) =
                make_float2(acc[mi][ni][2], acc[mi][ni][3]);
        }
    }
}

// ===========================================================================
// Fast check: one sample per 128x128 tile vs validated g_Wp. 2048 blocks.
// ===========================================================================
__global__ void check_kernel(const float* __restrict__ out,
                             const float* __restrict__ x) {
    const int b = blockIdx.x;                       // 0..2047
    const int m = (b >> 5) * 128 + ((b * 37) & 127);
    const int n = (b & 31) * 128 + ((b * 59) & 127);
    const int t = threadIdx.x;                      // 128
    float s = 0.f;
    for (int k = t; k < DIN; k += 128)
        s = fmaf(x[(size_t)m * DIN + k], g_Wp[(size_t)k * DOUT + n], s);
    __shared__ float red[128];
    red[t] = s;
    __syncthreads();
    for (int o = 64; o > 0; o >>= 1) {
        if (t < o) red[t] += red[t + o];
        __syncthreads();
    }
    if (t == 0) {
        float acc = red[0];
        float got = out[(size_t)m * DOUT + n];
        if (fabsf(got - acc) > 0.05f + 0.02f * fabsf(acc))
            atomicAdd(&g_flag, 1);
    }
}

// ===========================================================================
// Fallback: exact fp32 via packed fma.rn.f32x2 (validated). Gated on g_flag.
// ===========================================================================
static constexpr int P2 = 132;

__global__ __launch_bounds__(256, 2)
void gemm_f32x2_kernel(const float* __restrict__ x, float* __restrict__ out) {
    if (g_flag == 0) return;
    __shared__ __align__(16) float Xs[2][16][P2];
    __shared__ __align__(16) float Ws[2][16][P2];
    const int t = threadIdx.x;
    const int tm2 = t >> 4, tn2 = t & 15;

    const int bid = blockIdx.x;
    const int m0 = ((bid >> 8) * 8 + (bid & 7)) * 128;
    const int n0 = ((bid & 255) >> 3) * 128;

    unsigned long long acc2[8][4];
#pragma unroll
    for (int i = 0; i < 8; i++)
#pragma unroll
        for (int j = 0; j < 4; j++) acc2[i][j] = 0ULL;

    float4 rx[2], rw[2];
    auto LOADG = [&](int kc) {
#pragma unroll
        for (int j = 0; j < 2; j++) {
            int idx = j * 256 + t;
            int m = idx >> 2, q = idx & 3;
            rx[j] = *reinterpret_cast<const float4*>(
                x + (size_t)(m0 + m) * DIN + kc + q * 4);
            int kk = idx >> 5, qn = idx & 31;
            rw[j] = *reinterpret_cast<const float4*>(
                g_Wp + (size_t)(kc + kk) * DOUT + n0 + qn * 4);
        }
    };
    auto STORES = [&](int buf) {
#pragma unroll
        for (int j = 0; j < 2; j++) {
            int idx = j * 256 + t;
            int m = idx >> 2, q = idx & 3;
            Xs[buf][q * 4 + 0][m] = rx[j].x;
            Xs[buf][q * 4 + 1][m] = rx[j].y;
            Xs[buf][q * 4 + 2][m] = rx[j].z;
            Xs[buf][q * 4 + 3][m] = rx[j].w;
            int kk = idx >> 5, qn = idx & 31;
            *reinterpret_cast<float4*>(&Ws[buf][kk][qn * 4]) = rw[j];
        }
    };

    LOADG(0);
    STORES(0);
    __syncthreads();

    for (int i = 0; i < DIN / 16; i++) {
        if (i + 1 < DIN / 16) LOADG((i + 1) * 16);
        const int buf = i & 1;
#pragma unroll
        for (int kk = 0; kk < 16; kk++) {
            unsigned long long b2[4];
#pragma unroll
            for (int jj = 0; jj < 4; jj++)
                b2[jj] = *reinterpret_cast<const unsigned long long*>(
                    &Ws[buf][kk][tn2 * 2 + 32 * jj]);
#pragma unroll
            for (int ii = 0; ii < 8; ii++) {
                unsigned long long a2 = dup2(Xs[buf][kk][tm2 + 16 * ii]);
#pragma unroll
                for (int jj = 0; jj < 4; jj++)
                    fma2(acc2[ii][jj], a2, b2[jj]);
            }
        }
        if (i + 1 < DIN / 16) STORES(buf ^ 1);
        __syncthreads();
    }

#pragma unroll
    for (int ii = 0; ii < 8; ii++) {
        const int row = m0 + tm2 + 16 * ii;
#pragma unroll
        for (int jj = 0; jj < 4; jj++) {
            uint32_t lo, hi;
            asm("mov.b64 {%0, %1}, %2;" : "=r"(lo), "=r"(hi) : "l"(acc2[ii][jj]));
            *reinterpret_cast<float2*>(out + (size_t)row * DOUT + n0 + tn2 * 2 + 32 * jj) =
                make_float2(__uint_as_float(lo), __uint_as_float(hi));
        }
    }
}

// ---------------------------------------------------------------------------
extern "C" void kernel_launch(void* const* d_in, const int* in_sizes, int n_in,
                              void* d_out, int out_size) {
    const float *x = nullptr, *W = nullptr, *bias = nullptr;
    const float *P0 = nullptr, *P1 = nullptr;
    for (int i = 0; i < n_in; i++) {
        const float* p = (const float*)d_in[i];
        int sz = in_sizes[i];
        if      (sz == SEQ * DIN)   x = p;
        else if (sz == DIN * DOUT)  W = p;
        else if (sz == DOUT)        bias = p;
        else if (sz == DIN * RANK) { if (!P0) P0 = p; else P1 = p; }
    }
    if (!x || !W || !bias || !P0 || !P1) {
        x = (const float*)d_in[0]; W = (const float*)d_in[1];
        bias = (const float*)d_in[2];
        P0 = (const float*)d_in[3]; P1 = (const float*)d_in[4];
    }
    float* out = (float*)d_out;

    id_kernel<<<1, 256>>>(P0);
    prep_kn_kernel<<<dim3(DOUT / 32, DIN / 32), dim3(32, 8)>>>(W, P0, P1);

    if (out_size >= SEQ * DOUT + DOUT)
        bias_copy_kernel<<<(DOUT + 255) / 256, 256>>>(bias, out + (size_t)SEQ * DOUT);

    gemm_mma_kernel<<<FMT * FNT, 256>>>(x, out);
    check_kernel<<<2048, 128>>>(out, x);
    gemm_f32x2_kernel<<<FMT * FNT, 256>>>(x, out);
}

// round 14
// speedup vs baseline: 7.4482x; 1.0630x over previous
#include <cuda_runtime.h>
#include <cstdint>

// ===========================================================================
// LoRALinear: out = x @ (W + A@B); bias tail written only if out_size has room.
//   x:[8192,4096] W:[4096,4096] bias:[4096] A:[4096,16] B:[16,4096], all f32
//
// R14 (from R13 WIN @2191us): ncu showed l1tex=77%, tensor=43% -> smem-bound.
//   - GEMM: warp tile 64x32 -> 64x64 (4 warps/CTA, 128 thr), 1.5x fewer LDS
//     bytes per MAC. CTA 128x128, BK=16, reg-double-buffered plain-LDG
//     pipeline (validated R13). Fragment mapping = probe-verified, ni 4->8.
//   - prep / check / f32x2 fallback unchanged (validated).
// ===========================================================================

#define SEQ  8192
#define DIN  4096
#define DOUT 4096
#define RANK 16

__device__ float g_Wp [(size_t)DIN * DOUT];   // 64 MB [k][n] exact W+lora
__device__ float g_WpT[(size_t)DOUT * DIN];   // 64 MB [n][k] rna(tf32)
__device__ int   g_flag;
__device__ int   g_ab_swap;

// ---------------- helpers ---------------------------------------------------
__device__ __forceinline__ float rna_tf32(float v) {
    uint32_t b;
    asm("cvt.rna.tf32.f32 %0, %1;" : "=r"(b) : "f"(v));
    return __uint_as_float(b);
}
__device__ __forceinline__ void mma_tf32(float* c, const uint32_t* a, const uint32_t* b) {
    asm volatile(
        "mma.sync.aligned.m16n8k8.row.col.f32.tf32.tf32.f32 "
        "{%0,%1,%2,%3}, {%4,%5,%6,%7}, {%8,%9}, {%0,%1,%2,%3};"
        : "+f"(c[0]), "+f"(c[1]), "+f"(c[2]), "+f"(c[3])
        : "r"(a[0]), "r"(a[1]), "r"(a[2]), "r"(a[3]), "r"(b[0]), "r"(b[1]));
}
__device__ __forceinline__ void fma2(unsigned long long& d,
                                     unsigned long long a, unsigned long long b) {
    asm("fma.rn.f32x2 %0, %1, %2, %0;" : "+l"(d) : "l"(a), "l"(b));
}
__device__ __forceinline__ unsigned long long dup2(float v) {
    unsigned long long r;
    uint32_t b = __float_as_uint(v);
    asm("mov.b64 %0, {%1, %1};" : "=l"(r) : "r"(b));
    return r;
}

// ---------------------------------------------------------------------------
// id: A vs B by mean-square (A scaled 1/sqrt(4096)); reset g_flag.
// ---------------------------------------------------------------------------
__global__ void id_kernel(const float* __restrict__ P0) {
    __shared__ float red[256];
    const int t = threadIdx.x;
    float s = 0.f;
    for (int i = t; i < 16384; i += 256) { float v = P0[i]; s += v * v; }
    red[t] = s;
    __syncthreads();
    for (int off = 128; off > 0; off >>= 1) {
        if (t < off) red[t] += red[t + off];
        __syncthreads();
    }
    if (t == 0) {
        g_ab_swap = (red[0] * (1.f / 16384.f) > 0.05f) ? 1 : 0;
        g_flag = 0;
    }
}

// ---------------------------------------------------------------------------
// prep: g_Wp[k][n] = W + lora (exact)  AND  g_WpT[n][k] = rna(g_Wp) fused.
// ---------------------------------------------------------------------------
__global__ void prep_kn_kernel(const float* __restrict__ W,
                               const float* __restrict__ P0,
                               const float* __restrict__ P1) {
    const float* A = g_ab_swap ? P1 : P0;
    const float* B = g_ab_swap ? P0 : P1;
    __shared__ float tA[32][17];
    __shared__ float tB[16][33];
    __shared__ float tO[32][33];
    const int n0 = blockIdx.x * 32;
    const int k0 = blockIdx.y * 32;
    const int tx = threadIdx.x, ty = threadIdx.y;   // 32 x 8
    const int t = ty * 32 + tx;
#pragma unroll
    for (int i = 0; i < 2; i++) {
        int e = t + 256 * i;
        tA[e / 16][e % 16] = A[(size_t)(k0 + e / 16) * RANK + (e % 16)];
        tB[e / 32][e % 32] = B[(size_t)(e / 32) * DOUT + n0 + (e % 32)];
    }
    __syncthreads();
#pragma unroll
    for (int i = 0; i < 4; i++) {
        int kk = ty + 8 * i;
        float acc = W[(size_t)(k0 + kk) * DOUT + n0 + tx];
#pragma unroll
        for (int r = 0; r < RANK; r++) acc = fmaf(tA[kk][r], tB[r][tx], acc);
        g_Wp[(size_t)(k0 + kk) * DOUT + n0 + tx] = acc;
        tO[kk][tx] = acc;
    }
    __syncthreads();
#pragma unroll
    for (int i = 0; i < 4; i++) {
        int nn = ty + 8 * i;
        g_WpT[(size_t)(n0 + nn) * DIN + k0 + tx] = rna_tf32(tO[tx][nn]);
    }
}

__global__ void bias_copy_kernel(const float* __restrict__ b, float* __restrict__ dst) {
    int i = blockIdx.x * 256 + threadIdx.x;
    if (i < DOUT) dst[i] = b[i];
}

// ===========================================================================
// PRIMARY: mma tf32 GEMM. CTA 128x128, BK=16, 128 threads = 4 warps (2x2),
// warp tile 64x64 (mi 0..3 x ni 0..7). Reg-double-buffered plain-LDG pipeline.
// Static smem 2 x 2 x 128 x 20 x 4 = 40960 B.
// ===========================================================================
static constexpr int APAD = 20;            // (20g+tq) mod 32 hits all 32 banks
static constexpr int FNT = DOUT / 128;     // 32
static constexpr int FMT = SEQ / 128;      // 64

__global__ __launch_bounds__(128, 2)
void gemm_mma_kernel(const float* __restrict__ x, float* __restrict__ out) {
    __shared__ __align__(16) float sA[2][128 * APAD];
    __shared__ __align__(16) float sB[2][128 * APAD];
    const int tid = threadIdx.x;                       // 128
    const int wid = tid >> 5, lid = tid & 31;
    const int g = lid >> 2, tq = lid & 3;
    const int wm0 = (wid >> 1) * 64;                   // warps 2x2 over 128x128
    const int wn0 = (wid & 1) * 64;

    // supertile swizzle: groups of 8 m-tiles sweep all n-tiles (L2 reuse)
    const int bid = blockIdx.x;
    const int m0 = ((bid >> 8) * 8 + (bid & 7)) * 128;
    const int n0 = ((bid & 255) >> 3) * 128;

    const int ldrow = tid >> 2, ldq = tid & 3;         // rows 0..31, q 0..3
    const float* gx = x     + (size_t)(m0 + ldrow) * DIN + ldq * 4;
    const float* gw = g_WpT + (size_t)(n0 + ldrow) * DIN + ldq * 4;

    float acc[4][8][4];
#pragma unroll
    for (int i = 0; i < 4; i++)
#pragma unroll
        for (int j = 0; j < 8; j++)
#pragma unroll
            for (int q = 0; q < 4; q++) acc[i][j][q] = 0.f;

    float4 ra[4], rb[4];                               // 4 row-passes each
    auto LOADG = [&](int kc) {
#pragma unroll
        for (int p = 0; p < 4; p++) {
            ra[p] = *reinterpret_cast<const float4*>(gx + (size_t)(32 * p) * DIN + kc);
            rb[p] = *reinterpret_cast<const float4*>(gw + (size_t)(32 * p) * DIN + kc);
        }
    };
    auto STORES = [&](int buf) {
#pragma unroll
        for (int p = 0; p < 4; p++) {
            float4 va = ra[p];
            va.x = rna_tf32(va.x); va.y = rna_tf32(va.y);
            va.z = rna_tf32(va.z); va.w = rna_tf32(va.w);
            *reinterpret_cast<float4*>(&sA[buf][(ldrow + 32 * p) * APAD + ldq * 4]) = va;
            *reinterpret_cast<float4*>(&sB[buf][(ldrow + 32 * p) * APAD + ldq * 4]) = rb[p];
        }
    };

    LOADG(0);
    STORES(0);
    __syncthreads();

    for (int i = 0; i < DIN / 16; i++) {
        if (i + 1 < DIN / 16) LOADG((i + 1) * 16);

        const int buf = i & 1;
        const uint32_t* As = reinterpret_cast<const uint32_t*>(sA[buf]);
        const uint32_t* Bs = reinterpret_cast<const uint32_t*>(sB[buf]);
#pragma unroll
        for (int kb = 0; kb < 2; kb++) {
            uint32_t af[4][4], bf[8][2];
            const int kc = kb * 8 + tq;
#pragma unroll
            for (int mi = 0; mi < 4; mi++) {
                const uint32_t* p = As + (wm0 + mi * 16 + g) * APAD + kc;
                af[mi][0] = p[0];
                af[mi][1] = p[8 * APAD];
                af[mi][2] = p[4];
                af[mi][3] = p[8 * APAD + 4];
            }
#pragma unroll
            for (int ni = 0; ni < 8; ni++) {
                const uint32_t* p = Bs + (wn0 + ni * 8 + g) * APAD + kc;
                bf[ni][0] = p[0];
                bf[ni][1] = p[4];
            }
#pragma unroll
            for (int mi = 0; mi < 4; mi++)
#pragma unroll
                for (int ni = 0; ni < 8; ni++)
                    mma_tf32(acc[mi][ni], af[mi], bf[ni]);
        }

        if (i + 1 < DIN / 16) STORES(buf ^ 1);   // buf^1 reads finished at i-1
        __syncthreads();
    }

#pragma unroll
    for (int mi = 0; mi < 4; mi++) {
        const int row = m0 + wm0 + mi * 16 + g;
#pragma unroll
        for (int ni = 0; ni < 8; ni++) {
            const int col = n0 + wn0 + ni * 8 + tq * 2;
            *reinterpret_cast<float2*>(out + (size_t)row * DOUT + col) =
                make_float2(acc[mi][ni][0], acc[mi][ni][1]);
            *reinterpret_cast<float2*>(out + (size_t)(row + 8) * DOUT + col) =
                make_float2(acc[mi][ni][2], acc[mi][ni][3]);
        }
    }
}

// ===========================================================================
// Fast check: one sample per 128x128 tile vs validated g_Wp. 2048 blocks.
// ===========================================================================
__global__ void check_kernel(const float* __restrict__ out,
                             const float* __restrict__ x) {
    const int b = blockIdx.x;                       // 0..2047
    const int m = (b >> 5) * 128 + ((b * 37) & 127);
    const int n = (b & 31) * 128 + ((b * 59) & 127);
    const int t = threadIdx.x;                      // 128
    float s = 0.f;
    for (int k = t; k < DIN; k += 128)
        s = fmaf(x[(size_t)m * DIN + k], g_Wp[(size_t)k * DOUT + n], s);
    __shared__ float red[128];
    red[t] = s;
    __syncthreads();
    for (int o = 64; o > 0; o >>= 1) {
        if (t < o) red[t] += red[t + o];
        __syncthreads();
    }
    if (t == 0) {
        float acc = red[0];
        float got = out[(size_t)m * DOUT + n];
        if (fabsf(got - acc) > 0.05f + 0.02f * fabsf(acc))
            atomicAdd(&g_flag, 1);
    }
}

// ===========================================================================
// Fallback: exact fp32 via packed fma.rn.f32x2 (validated). Gated on g_flag.
// ===========================================================================
static constexpr int P2 = 132;

__global__ __launch_bounds__(256, 2)
void gemm_f32x2_kernel(const float* __restrict__ x, float* __restrict__ out) {
    if (g_flag == 0) return;
    __shared__ __align__(16) float Xs[2][16][P2];
    __shared__ __align__(16) float Ws[2][16][P2];
    const int t = threadIdx.x;
    const int tm2 = t >> 4, tn2 = t & 15;

    const int bid = blockIdx.x;
    const int m0 = ((bid >> 8) * 8 + (bid & 7)) * 128;
    const int n0 = ((bid & 255) >> 3) * 128;

    unsigned long long acc2[8][4];
#pragma unroll
    for (int i = 0; i < 8; i++)
#pragma unroll
        for (int j = 0; j < 4; j++) acc2[i][j] = 0ULL;

    float4 rx[2], rw[2];
    auto LOADG = [&](int kc) {
#pragma unroll
        for (int j = 0; j < 2; j++) {
            int idx = j * 256 + t;
            int m = idx >> 2, q = idx & 3;
            rx[j] = *reinterpret_cast<const float4*>(
                x + (size_t)(m0 + m) * DIN + kc + q * 4);
            int kk = idx >> 5, qn = idx & 31;
            rw[j] = *reinterpret_cast<const float4*>(
                g_Wp + (size_t)(kc + kk) * DOUT + n0 + qn * 4);
        }
    };
    auto STORES = [&](int buf) {
#pragma unroll
        for (int j = 0; j < 2; j++) {
            int idx = j * 256 + t;
            int m = idx >> 2, q = idx & 3;
            Xs[buf][q * 4 + 0][m] = rx[j].x;
            Xs[buf][q * 4 + 1][m] = rx[j].y;
            Xs[buf][q * 4 + 2][m] = rx[j].z;
            Xs[buf][q * 4 + 3][m] = rx[j].w;
            int kk = idx >> 5, qn = idx & 31;
            *reinterpret_cast<float4*>(&Ws[buf][kk][qn * 4]) = rw[j];
        }
    };

    LOADG(0);
    STORES(0);
    __syncthreads();

    for (int i = 0; i < DIN / 16; i++) {
        if (i + 1 < DIN / 16) LOADG((i + 1) * 16);
        const int buf = i & 1;
#pragma unroll
        for (int kk = 0; kk < 16; kk++) {
            unsigned long long b2[4];
#pragma unroll
            for (int jj = 0; jj < 4; jj++)
                b2[jj] = *reinterpret_cast<const unsigned long long*>(
                    &Ws[buf][kk][tn2 * 2 + 32 * jj]);
#pragma unroll
            for (int ii = 0; ii < 8; ii++) {
                unsigned long long a2 = dup2(Xs[buf][kk][tm2 + 16 * ii]);
#pragma unroll
                for (int jj = 0; jj < 4; jj++)
                    fma2(acc2[ii][jj], a2, b2[jj]);
            }
        }
        if (i + 1 < DIN / 16) STORES(buf ^ 1);
        __syncthreads();
    }

#pragma unroll
    for (int ii = 0; ii < 8; ii++) {
        const int row = m0 + tm2 + 16 * ii;
#pragma unroll
        for (int jj = 0; jj < 4; jj++) {
            uint32_t lo, hi;
            asm("mov.b64 {%0, %1}, %2;" : "=r"(lo), "=r"(hi) : "l"(acc2[ii][jj]));
            *reinterpret_cast<float2*>(out + (size_t)row * DOUT + n0 + tn2 * 2 + 32 * jj) =
                make_float2(__uint_as_float(lo), __uint_as_float(hi));
        }
    }
}

// ---------------------------------------------------------------------------
extern "C" void kernel_launch(void* const* d_in, const int* in_sizes, int n_in,
                              void* d_out, int out_size) {
    const float *x = nullptr, *W = nullptr, *bias = nullptr;
    const float *P0 = nullptr, *P1 = nullptr;
    for (int i = 0; i < n_in; i++) {
        const float* p = (const float*)d_in[i];
        int sz = in_sizes[i];
        if      (sz == SEQ * DIN)   x = p;
        else if (sz == DIN * DOUT)  W = p;
        else if (sz == DOUT)        bias = p;
        else if (sz == DIN * RANK) { if (!P0) P0 = p; else P1 = p; }
    }
    if (!x || !W || !bias || !P0 || !P1) {
        x = (const float*)d_in[0]; W = (const float*)d_in[1];
        bias = (const float*)d_in[2];
        P0 = (const float*)d_in[3]; P1 = (const float*)d_in[4];
    }
    float* out = (float*)d_out;

    id_kernel<<<1, 256>>>(P0);
    prep_kn_kernel<<<dim3(DOUT / 32, DIN / 32), dim3(32, 8)>>>(W, P0, P1);

    if (out_size >= SEQ * DOUT + DOUT)
        bias_copy_kernel<<<(DOUT + 255) / 256, 256>>>(bias, out + (size_t)SEQ * DOUT);

    gemm_mma_kernel<<<FMT * FNT, 128>>>(x, out);
    check_kernel<<<2048, 128>>>(out, x);
    gemm_f32x2_kernel<<<FMT * FNT, 256>>>(x, out);
}